// round 2
// baseline (speedup 1.0000x reference)
#include <cuda_runtime.h>
#include <math.h>

#define BB 32
#define SS 4096
#define DD 512          // INDIM == OUTDIM == 512
#define NCH 16
#define CS (SS / NCH)   // 256 keys per chunk

// ---- scratch (no allocations allowed) ----
__device__ float g_ht[BB * DD];          // 64 KB
__device__ float g_scores[BB * SS];      // 512 KB (raw masked scores)
__device__ float g_pm[BB * NCH];
__device__ float g_ps[BB * NCH];
__device__ float g_pc[BB * NCH * DD];    // 1 MB partial contexts
__device__ float g_cfin[BB * DD];

// memory_lengths may arrive as int32 or int64. Lengths are in [S/2, S] so the
// second 32-bit word is 0 iff the buffer is int64 (little-endian high word).
__device__ __forceinline__ int get_len(const int* __restrict__ L, int b) {
    return (L[1] == 0) ? L[2 * b] : L[b];
}

__device__ __forceinline__ float warp_allreduce_sum(float v) {
#pragma unroll
    for (int off = 16; off > 0; off >>= 1)
        v += __shfl_xor_sync(0xffffffffu, v, off);
    return v;
}

// ---------------------------------------------------------------------------
// Kernel 1: h_t[b][o] = dot(source[b,:], W_in[o,:])   (warp per output)
// ---------------------------------------------------------------------------
__global__ void k_ht(const float* __restrict__ src, const float* __restrict__ Win) {
    int wid = threadIdx.x >> 5, lane = threadIdx.x & 31;
    int gw = blockIdx.x * 8 + wid;          // 0 .. B*D-1
    int b = gw >> 9, o = gw & 511;
    const float4* s4 = (const float4*)(src + (size_t)b * DD);
    const float4* w4 = (const float4*)(Win + (size_t)o * DD);
    float dot = 0.f;
#pragma unroll
    for (int j = 0; j < 4; j++) {
        float4 a = s4[lane + 32 * j];
        float4 w = w4[lane + 32 * j];
        dot += a.x * w.x + a.y * w.y + a.z * w.z + a.w * w.w;
    }
    dot = warp_allreduce_sum(dot);
    if (lane == 0) g_ht[b * DD + o] = dot;
}

// ---------------------------------------------------------------------------
// Kernel 2: single-pass online-softmax attention over one (batch, chunk).
// Reads memory_bank exactly once — the 256 MB HBM-bound kernel.
// Two keys per iteration: 8 LDG.128 issued back-to-back for MLP=8/warp.
// ---------------------------------------------------------------------------
__global__ void __launch_bounds__(256) k_attn(const float* __restrict__ mb,
                                              const int* __restrict__ L) {
    __shared__ float  cbuf[8][DD];   // 16 KB: per-warp scaled context
    __shared__ float2 ms[8];         // per-warp (m, sum)

    int b = blockIdx.y, chunk = blockIdx.x;
    int wid = threadIdx.x >> 5, lane = threadIdx.x & 31;
    int len = get_len(L, b);
    int s0 = chunk * CS;
    int send = min(s0 + CS, len);

    // h_t[b] held in registers: lane owns float4 groups {lane+32j}
    const float4* h4 = (const float4*)(g_ht + b * DD);
    float4 h[4];
#pragma unroll
    for (int j = 0; j < 4; j++) h[j] = h4[lane + 32 * j];

    float m = -INFINITY, ssum = 0.f;
    float4 c[4];
#pragma unroll
    for (int j = 0; j < 4; j++) c[j] = make_float4(0.f, 0.f, 0.f, 0.f);

    const float* bbase = mb + (size_t)b * SS * DD;
    int s = s0 + wid;

    // main loop: 2 keys per iteration, all 8 loads issued before any SHFL
    for (; s + 8 < send; s += 16) {
        const float4* k4a = (const float4*)(bbase + (size_t)s * DD);
        const float4* k4b = (const float4*)(bbase + (size_t)(s + 8) * DD);
        float4 ka[4], kb[4];
#pragma unroll
        for (int j = 0; j < 4; j++) ka[j] = k4a[lane + 32 * j];
#pragma unroll
        for (int j = 0; j < 4; j++) kb[j] = k4b[lane + 32 * j];

        float da = 0.f, db = 0.f;
#pragma unroll
        for (int j = 0; j < 4; j++) {
            da += h[j].x * ka[j].x + h[j].y * ka[j].y
                + h[j].z * ka[j].z + h[j].w * ka[j].w;
            db += h[j].x * kb[j].x + h[j].y * kb[j].y
                + h[j].z * kb[j].z + h[j].w * kb[j].w;
        }
        float sa = warp_allreduce_sum(da);
        float sb = warp_allreduce_sum(db);
        if (lane == 0) {
            g_scores[b * SS + s]     = sa;
            g_scores[b * SS + s + 8] = sb;
        }

        float mn = fmaxf(fmaxf(sa, sb), m);
        float sc = (m == -INFINITY) ? 0.f : __expf(m - mn);
        float pa = __expf(sa - mn);
        float pb = __expf(sb - mn);
        ssum = ssum * sc + pa + pb;
#pragma unroll
        for (int j = 0; j < 4; j++) {
            c[j].x = c[j].x * sc + pa * ka[j].x + pb * kb[j].x;
            c[j].y = c[j].y * sc + pa * ka[j].y + pb * kb[j].y;
            c[j].z = c[j].z * sc + pa * ka[j].z + pb * kb[j].z;
            c[j].w = c[j].w * sc + pa * ka[j].w + pb * kb[j].w;
        }
        m = mn;
    }
    // tail: at most one key per warp
    if (s < send) {
        const float4* k4 = (const float4*)(bbase + (size_t)s * DD);
        float4 kv[4];
        float dot = 0.f;
#pragma unroll
        for (int j = 0; j < 4; j++) {
            kv[j] = k4[lane + 32 * j];
            dot += h[j].x * kv[j].x + h[j].y * kv[j].y
                 + h[j].z * kv[j].z + h[j].w * kv[j].w;
        }
        float score = warp_allreduce_sum(dot);
        if (lane == 0) g_scores[b * SS + s] = score;

        float mn = fmaxf(score, m);
        float sc = (m == -INFINITY) ? 0.f : __expf(m - mn);
        float p = __expf(score - mn);
        ssum = ssum * sc + p;
#pragma unroll
        for (int j = 0; j < 4; j++) {
            c[j].x = c[j].x * sc + p * kv[j].x;
            c[j].y = c[j].y * sc + p * kv[j].y;
            c[j].z = c[j].z * sc + p * kv[j].z;
            c[j].w = c[j].w * sc + p * kv[j].w;
        }
        m = mn;
    }

    if (lane == 0) ms[wid] = make_float2(m, ssum);
    __syncthreads();

    float M = -INFINITY;
#pragma unroll
    for (int w = 0; w < 8; w++) M = fmaxf(M, ms[w].x);

    float f = (m == -INFINITY) ? 0.f : __expf(m - M);
    float4* cb4 = (float4*)cbuf[wid];
#pragma unroll
    for (int j = 0; j < 4; j++) {
        float4 v = c[j];
        v.x *= f; v.y *= f; v.z *= f; v.w *= f;
        cb4[lane + 32 * j] = v;
    }
    __syncthreads();

    int pi = b * NCH + chunk;
    if (threadIdx.x == 0) {
        float Sc = 0.f;
#pragma unroll
        for (int w = 0; w < 8; w++) {
            float fm = ms[w].x;
            float fw = (fm == -INFINITY) ? 0.f : __expf(fm - M);
            Sc += ms[w].y * fw;
        }
        g_pm[pi] = M;
        g_ps[pi] = Sc;
    }
    // deterministic fixed-order cross-warp sum
    for (int d = threadIdx.x; d < DD; d += 256) {
        float acc = 0.f;
#pragma unroll
        for (int w = 0; w < 8; w++) acc += cbuf[w][d];
        g_pc[pi * DD + d] = acc;
    }
}

// ---------------------------------------------------------------------------
// Kernel 3: merge chunk partials -> final context; write align_vectors output.
// ---------------------------------------------------------------------------
__global__ void k_reduce(const int* __restrict__ L, float* __restrict__ out) {
    int b = blockIdx.x;
    int len = get_len(L, b);

    float M = -INFINITY;
#pragma unroll
    for (int i = 0; i < NCH; i++) M = fmaxf(M, g_pm[b * NCH + i]);

    float e[NCH];
    float Ssum = 0.f;
#pragma unroll
    for (int i = 0; i < NCH; i++) {
        float mi = g_pm[b * NCH + i];
        e[i] = (mi == -INFINITY) ? 0.f : __expf(mi - M);
        Ssum += g_ps[b * NCH + i] * e[i];
    }
    float invS = 1.f / Ssum;

    for (int d = threadIdx.x; d < DD; d += 256) {
        float acc = 0.f;
#pragma unroll
        for (int i = 0; i < NCH; i++) acc += g_pc[(b * NCH + i) * DD + d] * e[i];
        g_cfin[b * DD + d] = acc * invS;
    }

    float* ali = out + BB * DD + (size_t)b * SS;   // align output after attn_h
    for (int s = threadIdx.x; s < SS; s += 256)
        ali[s] = (s < len) ? __expf(g_scores[b * SS + s] - M) * invS : 0.f;
}

// ---------------------------------------------------------------------------
// Kernel 4: attn_h[b][o] = dot([c_final[b], source[b]], W_out[o,:])
// ---------------------------------------------------------------------------
__global__ void k_out(const float* __restrict__ src, const float* __restrict__ Wout,
                      float* __restrict__ out) {
    int wid = threadIdx.x >> 5, lane = threadIdx.x & 31;
    int gw = blockIdx.x * 8 + wid;
    int b = gw >> 9, o = gw & 511;
    const float4* w4 = (const float4*)(Wout + (size_t)o * (2 * DD)); // 256 float4
    const float4* c4 = (const float4*)(g_cfin + b * DD);
    const float4* s4 = (const float4*)(src + (size_t)b * DD);
    float dot = 0.f;
#pragma unroll
    for (int j = 0; j < 4; j++) {
        int i = lane + 32 * j;
        float4 w = w4[i];
        float4 x = c4[i];
        dot += w.x * x.x + w.y * x.y + w.z * x.z + w.w * x.w;
    }
#pragma unroll
    for (int j = 0; j < 4; j++) {
        int i = lane + 32 * j;
        float4 w = w4[128 + i];
        float4 x = s4[i];
        dot += w.x * x.x + w.y * x.y + w.z * x.z + w.w * x.w;
    }
    dot = warp_allreduce_sum(dot);
    if (lane == 0) out[b * DD + o] = dot;
}

// ---------------------------------------------------------------------------
extern "C" void kernel_launch(void* const* d_in, const int* in_sizes, int n_in,
                              void* d_out, int out_size) {
    const float* src  = (const float*)d_in[0];   // source        [32,1,512]
    const float* mb   = (const float*)d_in[1];   // memory_bank   [32,4096,512]
    const int*   L    = (const int*)  d_in[2];   // memory_lengths[32] (i32 or i64)
    const float* Win  = (const float*)d_in[3];   // W_in          [512,512]
    const float* Wout = (const float*)d_in[4];   // W_out         [512,1024]
    float* out = (float*)d_out;                  // [32*512 attn_h | 32*4096 align]

    k_ht    <<<(BB * DD) / 8, 256>>>(src, Win);
    k_attn  <<<dim3(NCH, BB), 256>>>(mb, L);
    k_reduce<<<BB, 256>>>(L, out);
    k_out   <<<(BB * DD) / 8, 256>>>(src, Wout, out);
}